// round 12
// baseline (speedup 1.0000x reference)
#include <cuda_runtime.h>
#include <cuda_fp16.h>
#include <cstdint>
#include <math.h>

// ---------------------------------------------------------------- constants
#define D_IN    2048
#define HEADS   16
#define GROUPS  2
#define HD      128
#define BATCH   8
#define SEQ     512
#define CACHE   256
#define T_TOT   768
#define M_ROWS  (BATCH*SEQ)                 // 4096
#define QKV_N   2560
#define OUT_O_SIZE (M_ROWS*D_IN)
#define OUT_K_SIZE (BATCH*T_TOT*GROUPS*HD)

// ---------------------------------------------------------------- scratch
__device__ __half g_xc[M_ROWS * D_IN];
__device__ float  g_qkv[M_ROWS * QKV_N];
__device__ __half g_q[M_ROWS * D_IN];               // roped+scaled q (b,h,s,hd)
__device__ __half g_attn[M_ROWS * D_IN];            // attention out (b,s,h*hd)
__device__ __half g_wT[QKV_N * D_IN];               // [n_qkv][2048]
__device__ __half g_woT[D_IN * D_IN];               // [n][2048]
__device__ __half g_kc[BATCH * T_TOT * GROUPS * HD];// roped k cache
__device__ __half g_vT[16 * HD * T_TOT];            // per bg: [hd][768]
__device__ float  g_bias[QKV_N];

// ---------------------------------------------------------------- helpers
__device__ __forceinline__ uint32_t smem_u32(const void* p) {
    uint32_t a;
    asm("{ .reg .u64 t; cvta.to.shared.u64 t, %1; cvt.u32.u64 %0, t; }" : "=r"(a) : "l"(p));
    return a;
}
__device__ __forceinline__ void mma_f16(float c[4],
                                        uint32_t a0, uint32_t a1, uint32_t a2, uint32_t a3,
                                        uint32_t b0, uint32_t b1) {
    asm volatile(
        "mma.sync.aligned.m16n8k16.row.col.f32.f16.f16.f32 "
        "{%0,%1,%2,%3}, {%4,%5,%6,%7}, {%8,%9}, {%0,%1,%2,%3};"
        : "+f"(c[0]), "+f"(c[1]), "+f"(c[2]), "+f"(c[3])
        : "r"(a0), "r"(a1), "r"(a2), "r"(a3), "r"(b0), "r"(b1));
}
__device__ __forceinline__ void ldsm_x4(uint32_t* r, uint32_t addr) {
    asm volatile("ldmatrix.sync.aligned.m8n8.x4.shared.b16 {%0,%1,%2,%3}, [%4];"
        : "=r"(r[0]), "=r"(r[1]), "=r"(r[2]), "=r"(r[3]) : "r"(addr));
}

#define CP_ASYNC16(dst, src) \
    asm volatile("cp.async.cg.shared.global [%0], [%1], 16;" :: "r"(dst), "l"(src) : "memory")
#define CP_COMMIT() asm volatile("cp.async.commit_group;" ::: "memory")
#define CP_WAIT1()  asm volatile("cp.async.wait_group 1;" ::: "memory")
#define CP_WAIT0()  asm volatile("cp.async.wait_group 0;" ::: "memory")

// ---------------------------------------------------------------- GEMM core (fp16, ldmatrix)
// CTA tile 128x128, K chunk 64 (4 ksteps of 16), 256 threads = 8 warps (4m x 2n),
// warp 32x64. 3-stage cp.async, one barrier per chunk. Row = 64 halves + 8 pad = 36 words.
#define SROWH 36
#define STAGE_WORDS (2 * 128 * SROWH)            // 9216 words = 36 KB
#define NSTAGE 3
#define GEMM_SMEM_BYTES (NSTAGE * STAGE_WORDS * 4)   // 110592

__device__ __forceinline__ void mma_gemm(
    const __half* __restrict__ A, int lda,
    const __half* __restrict__ B, int ldb,
    int n_chunks, float* sm, float c[2][8][4])
{
    const int tid  = threadIdx.x;
    const int lane = tid & 31;
    const int wid  = tid >> 5;
    const int wm   = wid >> 1;
    const int wn   = wid & 1;
    const uint32_t sbase = smem_u32(sm);

    const int srow = tid >> 1;        // 0..127
    const int cb   = (tid & 1) * 4;   // 16B chunk base (0 or 4) of 8 per row

    #pragma unroll
    for (int mt = 0; mt < 2; mt++)
        #pragma unroll
        for (int nt = 0; nt < 8; nt++)
            #pragma unroll
            for (int q = 0; q < 4; q++) c[mt][nt][q] = 0.f;

    auto issue = [&](int chunk, int stage) {
        if (chunk < n_chunks) {
            uint32_t sA = sbase + stage * (STAGE_WORDS * 4);
            uint32_t sB = sA + 128 * SROWH * 4;
            const __half* ap = A + (size_t)srow * lda + chunk * 64 + cb * 8;
            const __half* bp = B + (size_t)srow * ldb + chunk * 64 + cb * 8;
            uint32_t da = sA + (srow * SROWH + cb * 4) * 4;
            uint32_t db = sB + (srow * SROWH + cb * 4) * 4;
            #pragma unroll
            for (int q = 0; q < 4; q++) {
                CP_ASYNC16(da + q * 16, ap + q * 8);
                CP_ASYNC16(db + q * 16, bp + q * 8);
            }
        }
        CP_COMMIT();
    };

    // ldmatrix lane-address offsets (bytes)
    const uint32_t aoff = ((uint32_t)(wm * 32 + (lane & 15)) * SROWH + (lane >> 4) * 4) * 4;
    const uint32_t boff = ((uint32_t)(wn * 64 + ((lane >> 4) & 1) * 8 + (lane & 7)) * SROWH
                           + ((lane >> 3) & 1) * 4) * 4;

    auto compute = [&](int s) {
        uint32_t sA = sbase + s * (STAGE_WORDS * 4);
        uint32_t sB = sA + 128 * SROWH * 4;
        uint32_t aAddr = sA + aoff;
        uint32_t bAddr = sB + boff;
        #pragma unroll
        for (int ks = 0; ks < 4; ks++) {
            uint32_t af[2][4];
            ldsm_x4(af[0], aAddr + ks * 32);
            ldsm_x4(af[1], aAddr + 16 * SROWH * 4 + ks * 32);
            #pragma unroll
            for (int j = 0; j < 4; j++) {
                uint32_t bb[4];
                ldsm_x4(bb, bAddr + j * 16 * SROWH * 4 + ks * 32);
                mma_f16(c[0][2*j],   af[0][0], af[0][1], af[0][2], af[0][3], bb[0], bb[1]);
                mma_f16(c[1][2*j],   af[1][0], af[1][1], af[1][2], af[1][3], bb[0], bb[1]);
                mma_f16(c[0][2*j+1], af[0][0], af[0][1], af[0][2], af[0][3], bb[2], bb[3]);
                mma_f16(c[1][2*j+1], af[1][0], af[1][1], af[1][2], af[1][3], bb[2], bb[3]);
            }
        }
    };

    issue(0, 0);
    issue(1, 1);
    for (int i = 0; i < n_chunks; i++) {
        CP_WAIT1();                  // stage i ready (i+1 may be in flight)
        __syncthreads();             // all warps past compute(i-1)
        issue(i + 2, (i + 2) % NSTAGE);  // rewrites stage (i-1)%3 — safe after sync
        compute(i % NSTAGE);
    }
}

#define EPI_ROW(mt, half_)  (( (threadIdx.x >> 6) & 3 ) * 32 + (mt) * 16 + ((threadIdx.x & 31) >> 2) + (half_) * 8)
#define EPI_COL(nt)         (( (threadIdx.x >> 5) & 1 ) * 64 + (nt) * 8 + ((threadIdx.x & 31) & 3) * 2)

// ---------------------------------------------------------------- projection kernels

__global__ void __launch_bounds__(256, 2) qkv_gemm_kernel()
{
    extern __shared__ float sm[];
    int row0 = blockIdx.x * 128;
    int n0 = blockIdx.y * 128;

    float c[2][8][4];
    mma_gemm(g_xc + (size_t)row0 * D_IN, D_IN, g_wT + (size_t)n0 * D_IN, D_IN,
             D_IN / 64, sm, c);

    #pragma unroll
    for (int mt = 0; mt < 2; mt++)
        #pragma unroll
        for (int hf = 0; hf < 2; hf++) {
            int r = row0 + EPI_ROW(mt, hf);
            #pragma unroll
            for (int nt = 0; nt < 8; nt++) {
                int cl = EPI_COL(nt);
                float2 v;
                v.x = c[mt][nt][hf*2+0] + g_bias[n0 + cl];
                v.y = c[mt][nt][hf*2+1] + g_bias[n0 + cl + 1];
                *(float2*)&g_qkv[(size_t)r * QKV_N + n0 + cl] = v;
            }
        }
}

__global__ void __launch_bounds__(256, 2) outproj_gemm_kernel(
    const float* __restrict__ bo, float* __restrict__ out_o)
{
    extern __shared__ float sm[];
    int row0 = blockIdx.x * 128;
    int n0 = blockIdx.y * 128;

    float c[2][8][4];
    mma_gemm(g_attn + (size_t)row0 * D_IN, D_IN, g_woT + (size_t)n0 * D_IN, D_IN,
             D_IN / 64, sm, c);

    #pragma unroll
    for (int mt = 0; mt < 2; mt++)
        #pragma unroll
        for (int hf = 0; hf < 2; hf++) {
            int r = row0 + EPI_ROW(mt, hf);
            #pragma unroll
            for (int nt = 0; nt < 8; nt++) {
                int cl = EPI_COL(nt);
                float2 v;
                v.x = c[mt][nt][hf*2+0] + bo[n0 + cl];
                v.y = c[mt][nt][hf*2+1] + bo[n0 + cl + 1];
                *(float2*)&out_o[(size_t)r * D_IN + n0 + cl] = v;
            }
        }
}

// ---------------------------------------------------------------- fused flash attention (fp16, ldmatrix)
#define SROWFW 68
#define FLASH_TILE_W (128 * SROWFW)                   // 8704 words
#define FLASH_SMEM_BYTES ((3 * FLASH_TILE_W + 512) * 4)  // 106496

__global__ void __launch_bounds__(256, 1) flash_attn_kernel()
{
    extern __shared__ float sm[];
    uint32_t* KPw = (uint32_t*)sm + FLASH_TILE_W;
    float* redmax = sm + 3 * FLASH_TILE_W;   // [2][128]
    float* redsum = redmax + 256;            // [2][128]

    const int tid = threadIdx.x;
    const int lane = tid & 31;
    const int wid = tid >> 5;
    const int wm = wid >> 1;       // 0..3
    const int wn = wid & 1;        // 0..1

    const int bh = blockIdx.y;
    const int b = bh >> 4, h = bh & 15, g = h >> 3;
    const int bg = b * 2 + g;
    const int s0 = blockIdx.x * 128;

    const uint32_t sbase = smem_u32(sm);
    const uint32_t qb = sbase;
    const uint32_t kpb = sbase + FLASH_TILE_W * 4;
    const uint32_t vb = sbase + 2 * FLASH_TILE_W * 4;

    const int srow = tid >> 1;
    const int scb  = (tid & 1) * 8;

    // stage Q (group 0)
    {
        const __half* qsrc = g_q + (((size_t)b * HEADS + h) * SEQ + s0) * HD;
        #pragma unroll
        for (int q = 0; q < 8; q++)
            CP_ASYNC16(qb + (srow * SROWFW + (scb + q) * 4) * 4,
                       qsrc + (size_t)srow * HD + (scb + q) * 8);
        CP_COMMIT();
    }

    const __half* kptr = g_kc + ((size_t)b * T_TOT * GROUPS + g) * HD;
    const __half* vptr = g_vT + (size_t)bg * HD * T_TOT;

    float m_[2][2], l_[2][2], co[2][8][4];
    #pragma unroll
    for (int mt = 0; mt < 2; mt++)
        #pragma unroll
        for (int hf = 0; hf < 2; hf++) { m_[mt][hf] = -1e30f; l_[mt][hf] = 0.f; }
    #pragma unroll
    for (int mt = 0; mt < 2; mt++)
        #pragma unroll
        for (int nt = 0; nt < 8; nt++)
            #pragma unroll
            for (int q = 0; q < 4; q++) co[mt][nt][q] = 0.f;

    const uint32_t aoffF = ((uint32_t)(wm * 32 + (lane & 15)) * SROWFW + (lane >> 4) * 4) * 4;
    const uint32_t boffF = ((uint32_t)(wn * 64 + ((lane >> 4) & 1) * 8 + (lane & 7)) * SROWFW
                            + ((lane >> 3) & 1) * 4) * 4;
    const uint32_t aAddrQ = qb + aoffF;
    const uint32_t bAddrK = kpb + boffF;
    const uint32_t bAddrV = vb + boffF;
    const uint32_t aAddrP = kpb + aoffF;

    int myrow[2][2];
    #pragma unroll
    for (int mt = 0; mt < 2; mt++)
        #pragma unroll
        for (int hf = 0; hf < 2; hf++)
            myrow[mt][hf] = wm * 32 + mt * 16 + (lane >> 2) + hf * 8;

    for (int tc = 0; tc < T_TOT / 128; tc++) {
        const int t0 = tc * 128;
        #pragma unroll
        for (int q = 0; q < 8; q++)
            CP_ASYNC16(kpb + (srow * SROWFW + (scb + q) * 4) * 4,
                       kptr + (size_t)(t0 + srow) * (GROUPS * HD) + (scb + q) * 8);
        CP_COMMIT();
        #pragma unroll
        for (int q = 0; q < 8; q++)
            CP_ASYNC16(vb + (srow * SROWFW + (scb + q) * 4) * 4,
                       vptr + (size_t)srow * T_TOT + t0 + (scb + q) * 8);
        CP_COMMIT();
        CP_WAIT1();          // Q + K ready; V may lag
        __syncthreads();

        // ---- S = Q @ K^T
        float cs[2][8][4];
        #pragma unroll
        for (int mt = 0; mt < 2; mt++)
            #pragma unroll
            for (int nt = 0; nt < 8; nt++)
                #pragma unroll
                for (int q = 0; q < 4; q++) cs[mt][nt][q] = 0.f;

        #pragma unroll
        for (int ks = 0; ks < 8; ks++) {
            uint32_t af[2][4];
            ldsm_x4(af[0], aAddrQ + ks * 32);
            ldsm_x4(af[1], aAddrQ + 16 * SROWFW * 4 + ks * 32);
            #pragma unroll
            for (int j = 0; j < 4; j++) {
                uint32_t bb[4];
                ldsm_x4(bb, bAddrK + j * 16 * SROWFW * 4 + ks * 32);
                mma_f16(cs[0][2*j],   af[0][0], af[0][1], af[0][2], af[0][3], bb[0], bb[1]);
                mma_f16(cs[1][2*j],   af[1][0], af[1][1], af[1][2], af[1][3], bb[0], bb[1]);
                mma_f16(cs[0][2*j+1], af[0][0], af[0][1], af[0][2], af[0][3], bb[2], bb[3]);
                mma_f16(cs[1][2*j+1], af[1][0], af[1][1], af[1][2], af[1][3], bb[2], bb[3]);
            }
        }

        // ---- online softmax
        #pragma unroll
        for (int mt = 0; mt < 2; mt++)
            #pragma unroll
            for (int hf = 0; hf < 2; hf++) {
                float mx = -1e30f;
                #pragma unroll
                for (int nt = 0; nt < 8; nt++)
                    mx = fmaxf(mx, fmaxf(cs[mt][nt][hf*2], cs[mt][nt][hf*2+1]));
                mx = fmaxf(mx, __shfl_xor_sync(0xffffffffu, mx, 1));
                mx = fmaxf(mx, __shfl_xor_sync(0xffffffffu, mx, 2));
                if ((lane & 3) == 0) redmax[wn * 128 + myrow[mt][hf]] = mx;
            }
        __syncthreads();

        float sc[2][2];
        #pragma unroll
        for (int mt = 0; mt < 2; mt++)
            #pragma unroll
            for (int hf = 0; hf < 2; hf++) {
                int r = myrow[mt][hf];
                float mnew = fmaxf(m_[mt][hf], fmaxf(redmax[r], redmax[128 + r]));
                sc[mt][hf] = __expf(m_[mt][hf] - mnew);
                m_[mt][hf] = mnew;
            }

        // exp, partial sums, write P (fp16) into KP
        #pragma unroll
        for (int mt = 0; mt < 2; mt++)
            #pragma unroll
            for (int hf = 0; hf < 2; hf++) {
                int r = myrow[mt][hf];
                float mnew = m_[mt][hf];
                float sum = 0.f;
                __half2* prow = (__half2*)KPw + r * SROWFW + wn * 32 + (lane & 3);
                #pragma unroll
                for (int nt = 0; nt < 8; nt++) {
                    float p0 = __expf(cs[mt][nt][hf*2+0] - mnew);
                    float p1 = __expf(cs[mt][nt][hf*2+1] - mnew);
                    sum += p0 + p1;
                    prow[nt * 4] = __floats2half2_rn(p0, p1);
                }
                sum += __shfl_xor_sync(0xffffffffu, sum, 1);
                sum += __shfl_xor_sync(0xffffffffu, sum, 2);
                if ((lane & 3) == 0) redsum[wn * 128 + r] = sum;
            }
        CP_WAIT0();
        __syncthreads();   // P + redsum + V visible

        #pragma unroll
        for (int mt = 0; mt < 2; mt++)
            #pragma unroll
            for (int hf = 0; hf < 2; hf++) {
                int r = myrow[mt][hf];
                l_[mt][hf] = l_[mt][hf] * sc[mt][hf] + redsum[r] + redsum[128 + r];
                #pragma unroll
                for (int nt = 0; nt < 8; nt++) {
                    co[mt][nt][hf*2+0] *= sc[mt][hf];
                    co[mt][nt][hf*2+1] *= sc[mt][hf];
                }
            }

        // ---- O += P @ V^T
        #pragma unroll
        for (int ks = 0; ks < 8; ks++) {
            uint32_t af[2][4];
            ldsm_x4(af[0], aAddrP + ks * 32);
            ldsm_x4(af[1], aAddrP + 16 * SROWFW * 4 + ks * 32);
            #pragma unroll
            for (int j = 0; j < 4; j++) {
                uint32_t bb[4];
                ldsm_x4(bb, bAddrV + j * 16 * SROWFW * 4 + ks * 32);
                mma_f16(co[0][2*j],   af[0][0], af[0][1], af[0][2], af[0][3], bb[0], bb[1]);
                mma_f16(co[1][2*j],   af[1][0], af[1][1], af[1][2], af[1][3], bb[0], bb[1]);
                mma_f16(co[0][2*j+1], af[0][0], af[0][1], af[0][2], af[0][3], bb[2], bb[3]);
                mma_f16(co[1][2*j+1], af[1][0], af[1][1], af[1][2], af[1][3], bb[2], bb[3]);
            }
        }
        __syncthreads();
    }

    // ---- epilogue: normalize, write g_attn (fp16)
    #pragma unroll
    for (int mt = 0; mt < 2; mt++)
        #pragma unroll
        for (int hf = 0; hf < 2; hf++) {
            int r = myrow[mt][hf];
            float inv = 1.f / l_[mt][hf];
            __half2* dst = (__half2*)(g_attn + ((size_t)b * SEQ + s0 + r) * D_IN
                                      + h * HD + wn * 64 + (lane & 3) * 2);
            #pragma unroll
            for (int nt = 0; nt < 8; nt++)
                dst[nt * 4] = __floats2half2_rn(co[mt][nt][hf*2+0] * inv,
                                                co[mt][nt][hf*2+1] * inv);
        }
}

// ---------------------------------------------------------------- prep kernels

__global__ void cvt_x_kernel(const float* __restrict__ x)
{
    int i = blockIdx.x * blockDim.x + threadIdx.x;
    float4 v = ((const float4*)x)[i];
    ((__half2*)g_xc)[i * 2 + 0] = __floats2half2_rn(v.x, v.y);
    ((__half2*)g_xc)[i * 2 + 1] = __floats2half2_rn(v.z, v.w);
}

__device__ __forceinline__ void transpose_block(
    const float* __restrict__ src, __half* __restrict__ dst,
    int K, int N, int bx, int by, float* tbuf)
{
    // tbuf: 32x33 floats
    int n0 = bx * 32, k0 = by * 32;
    int tx = threadIdx.x, ty = threadIdx.y;
    #pragma unroll
    for (int j = 0; j < 32; j += 8)
        tbuf[(ty + j) * 33 + tx] = src[(size_t)(k0 + ty + j) * N + n0 + tx];
    __syncthreads();
    #pragma unroll
    for (int j = 0; j < 32; j += 8)
        dst[(size_t)(n0 + ty + j) * K + k0 + tx] = __float2half(tbuf[tx * 33 + ty + j]);
}

// All weight transposes + bias combine, one launch. blockDim (32,8).
// Regions: [0,4096) Wq, [4096,4608) Wk, [4608,5120) Wv, [5120,9216) Wo, [9216,9226) bias.
__global__ void prep_weights_kernel(
    const float* __restrict__ Wq, const float* __restrict__ Wk,
    const float* __restrict__ Wv, const float* __restrict__ Wo,
    const float* __restrict__ bq, const float* __restrict__ bk,
    const float* __restrict__ bv)
{
    __shared__ float tbuf[32 * 33];
    int bid = blockIdx.x;
    if (bid < 4096) {
        transpose_block(Wq, g_wT, D_IN, D_IN, bid & 63, bid >> 6, tbuf);
    } else if (bid < 4608) {
        int l = bid - 4096;
        transpose_block(Wk, g_wT + 2048 * D_IN, D_IN, 256, l & 7, l >> 3, tbuf);
    } else if (bid < 5120) {
        int l = bid - 4608;
        transpose_block(Wv, g_wT + 2304 * D_IN, D_IN, 256, l & 7, l >> 3, tbuf);
    } else if (bid < 9216) {
        int l = bid - 5120;
        transpose_block(Wo, g_woT, D_IN, D_IN, l & 63, l >> 6, tbuf);
    } else {
        int i = (bid - 9216) * 256 + threadIdx.y * 32 + threadIdx.x;
        if (i < QKV_N) {
            float v;
            if (i < 2048) v = bq[i];
            else if (i < 2304) v = bk[i - 2048];
            else v = bv[i - 2304];
            g_bias[i] = v;
        }
    }
}

// rope_q + rope_kv fused: idx < NQ -> q path, else kv path
#define NQ_THREADS (M_ROWS * HEADS * 64)    // 4194304
#define NKV_THREADS (M_ROWS * GROUPS * 64)  // 524288
__global__ void rope_all_kernel(float* __restrict__ out_k, float* __restrict__ out_v)
{
    int idx = blockIdx.x * blockDim.x + threadIdx.x;
    if (idx < NQ_THREADS) {
        int j = idx & 63;
        int h = (idx >> 6) & 15;
        int m = idx >> 10;
        const float* src = g_qkv + (size_t)m * QKV_N + h * HD;
        float x1 = src[j], x2 = src[j + 64];
        int s = m & 511, b = m >> 9;
        float pos = (float)(CACHE + s);
        float freq = pos * expf(-(float)j * (9.210340371976184f / 64.f));
        float sn, cs; sincosf(freq, &sn, &cs);
        const float SCALE = 0.08838834764831845f;
        __half* dst = g_q + (((size_t)b * HEADS + h) * SEQ + s) * HD;
        dst[j]      = __float2half((x1 * cs - x2 * sn) * SCALE);
        dst[j + 64] = __float2half((x2 * cs + x1 * sn) * SCALE);
    } else {
        int kidx = idx - NQ_THREADS;
        int j = kidx & 63;
        int g = (kidx >> 6) & 1;
        int m = kidx >> 7;
        const float* ksrc = g_qkv + (size_t)m * QKV_N + 2048 + g * HD;
        const float* vsrc = g_qkv + (size_t)m * QKV_N + 2304 + g * HD;
        float x1 = ksrc[j], x2 = ksrc[j + 64];
        int s = m & 511, b = m >> 9;
        float pos = (float)(CACHE + s);
        float freq = pos * expf(-(float)j * (9.210340371976184f / 64.f));
        float sn, cs; sincosf(freq, &sn, &cs);
        float k1 = x1 * cs - x2 * sn;
        float k2 = x2 * cs + x1 * sn;
        size_t base = (((size_t)b * T_TOT + CACHE + s) * GROUPS + g) * HD;
        out_k[base + j]      = k1;
        out_k[base + j + 64] = k2;
        g_kc[base + j]       = __float2half(k1);
        g_kc[base + j + 64]  = __float2half(k2);
        float v1 = vsrc[j], v2 = vsrc[j + 64];
        out_v[base + j]      = v1;
        out_v[base + j + 64] = v2;
        int bg = b * 2 + g;
        g_vT[(size_t)bg * HD * T_TOT + (size_t)j * T_TOT + CACHE + s]        = __float2half(v1);
        g_vT[(size_t)bg * HD * T_TOT + (size_t)(j + 64) * T_TOT + CACHE + s] = __float2half(v2);
    }
}

// prev cache copy + fp16 K cache + transposed-V history
__global__ void copy_prev_kernel(const float* __restrict__ prev_k,
                                 const float* __restrict__ prev_v,
                                 float* __restrict__ out_k,
                                 float* __restrict__ out_v)
{
    int idx = blockIdx.x * blockDim.x + threadIdx.x;
    if (idx >= BATCH * CACHE * GROUPS * HD) return;
    int b = idx >> 16;
    int r = idx & 65535;                 // ((t*GROUPS+g)*HD + hd)
    float kv = prev_k[idx];
    float vv = prev_v[idx];
    out_k[(size_t)b * (T_TOT * GROUPS * HD) + r] = kv;
    g_kc[(size_t)b * (T_TOT * GROUPS * HD) + r]  = __float2half(kv);
    out_v[(size_t)b * (T_TOT * GROUPS * HD) + r] = vv;
    int t = r >> 8;
    int g = (r >> 7) & 1;
    int hd = r & 127;
    g_vT[(size_t)(b * 2 + g) * HD * T_TOT + (size_t)hd * T_TOT + t] = __float2half(vv);
}

// ---------------------------------------------------------------- launcher
extern "C" void kernel_launch(void* const* d_in, const int* in_sizes, int n_in,
                              void* d_out, int out_size)
{
    const float* x      = (const float*)d_in[0];
    const float* prev_k = (const float*)d_in[1];
    const float* prev_v = (const float*)d_in[2];
    const float* Wq     = (const float*)d_in[3];
    const float* bq     = (const float*)d_in[4];
    const float* Wk     = (const float*)d_in[5];
    const float* bk     = (const float*)d_in[6];
    const float* Wv     = (const float*)d_in[7];
    const float* bv     = (const float*)d_in[8];
    const float* Wo     = (const float*)d_in[9];
    const float* bo     = (const float*)d_in[10];

    float* out_o = (float*)d_out;
    float* out_k = out_o + OUT_O_SIZE;
    float* out_v = out_k + OUT_K_SIZE;

    static bool attr_set = false;
    if (!attr_set) {
        cudaFuncSetAttribute(qkv_gemm_kernel,     cudaFuncAttributeMaxDynamicSharedMemorySize, GEMM_SMEM_BYTES);
        cudaFuncSetAttribute(outproj_gemm_kernel, cudaFuncAttributeMaxDynamicSharedMemorySize, GEMM_SMEM_BYTES);
        cudaFuncSetAttribute(flash_attn_kernel,   cudaFuncAttributeMaxDynamicSharedMemorySize, FLASH_SMEM_BYTES);
        attr_set = true;
    }

    // 0. Operand preparation (2 launches)
    cvt_x_kernel<<<(M_ROWS * D_IN / 4) / 256, 256>>>(x);
    prep_weights_kernel<<<9226, dim3(32, 8)>>>(Wq, Wk, Wv, Wo, bq, bk, bv);

    // 1. kv-cache history
    copy_prev_kernel<<<2048, 256>>>(prev_k, prev_v, out_k, out_v);

    // 2. QKV projection
    qkv_gemm_kernel<<<dim3(M_ROWS / 128, QKV_N / 128), 256, GEMM_SMEM_BYTES>>>();

    // 3. RoPE q + k + v copy + transposed V (one launch)
    rope_all_kernel<<<(NQ_THREADS + NKV_THREADS) / 256, 256>>>(out_k, out_v);

    // 4. Fused flash attention
    flash_attn_kernel<<<dim3(SEQ / 128, BATCH * HEADS), 256, FLASH_SMEM_BYTES>>>();

    // 5. Output projection
    outproj_gemm_kernel<<<dim3(M_ROWS / 128, D_IN / 128), 256, GEMM_SMEM_BYTES>>>(bo, out_o);
}

// round 13
// speedup vs baseline: 1.2703x; 1.2703x over previous
#include <cuda_runtime.h>
#include <cuda_fp16.h>
#include <cstdint>
#include <math.h>

// ---------------------------------------------------------------- constants
#define D_IN    2048
#define HEADS   16
#define GROUPS  2
#define HD      128
#define BATCH   8
#define SEQ     512
#define CACHE   256
#define T_TOT   768
#define M_ROWS  (BATCH*SEQ)                 // 4096
#define QKV_N   2560
#define OUT_O_SIZE (M_ROWS*D_IN)
#define OUT_K_SIZE (BATCH*T_TOT*GROUPS*HD)

// ---------------------------------------------------------------- scratch
__device__ __half g_xc[M_ROWS * D_IN];
__device__ float  g_qkv[M_ROWS * QKV_N];
__device__ __half g_q[M_ROWS * D_IN];               // roped+scaled q (b,h,s,hd)
__device__ __half g_attn[M_ROWS * D_IN];            // attention out (b,s,h*hd)
__device__ __half g_wT[QKV_N * D_IN];               // [n_qkv][2048]
__device__ __half g_woT[D_IN * D_IN];               // [n][2048]
__device__ __half g_kc[BATCH * T_TOT * GROUPS * HD];// roped k cache
__device__ __half g_vT[16 * HD * T_TOT];            // per bg: [hd][768]
__device__ float  g_bias[QKV_N];

// ---------------------------------------------------------------- helpers
__device__ __forceinline__ uint32_t smem_u32(const void* p) {
    uint32_t a;
    asm("{ .reg .u64 t; cvta.to.shared.u64 t, %1; cvt.u32.u64 %0, t; }" : "=r"(a) : "l"(p));
    return a;
}
__device__ __forceinline__ void mma_f16(float c[4],
                                        uint32_t a0, uint32_t a1, uint32_t a2, uint32_t a3,
                                        uint32_t b0, uint32_t b1) {
    asm volatile(
        "mma.sync.aligned.m16n8k16.row.col.f32.f16.f16.f32 "
        "{%0,%1,%2,%3}, {%4,%5,%6,%7}, {%8,%9}, {%0,%1,%2,%3};"
        : "+f"(c[0]), "+f"(c[1]), "+f"(c[2]), "+f"(c[3])
        : "r"(a0), "r"(a1), "r"(a2), "r"(a3), "r"(b0), "r"(b1));
}
__device__ __forceinline__ void ldsm_x4(uint32_t* r, uint32_t addr) {
    asm volatile("ldmatrix.sync.aligned.m8n8.x4.shared.b16 {%0,%1,%2,%3}, [%4];"
        : "=r"(r[0]), "=r"(r[1]), "=r"(r[2]), "=r"(r[3]) : "r"(addr));
}

#define CP_ASYNC16(dst, src) \
    asm volatile("cp.async.cg.shared.global [%0], [%1], 16;" :: "r"(dst), "l"(src) : "memory")
#define CP_COMMIT() asm volatile("cp.async.commit_group;" ::: "memory")
#define CP_WAIT2()  asm volatile("cp.async.wait_group 2;" ::: "memory")
#define CP_WAIT1()  asm volatile("cp.async.wait_group 1;" ::: "memory")
#define CP_WAIT0()  asm volatile("cp.async.wait_group 0;" ::: "memory")

// ---------------------------------------------------------------- GEMM core (fp16, ldmatrix)
// ROUND-11 PROVEN CONFIG: CTA tile 128x128, K chunk 32 (2 ksteps of 16), 256 threads
// = 8 warps (4m x 2n), warp 32x64. 4-stage cp.async (80 KB -> 2 CTAs/SM),
// ONE barrier per chunk. Rows: 32 halves + pad = 20 words.
#define SROWH 20
#define STAGE_WORDS (2 * 128 * SROWH)            // 5120 words = 20 KB
#define NSTAGE 4
#define GEMM_SMEM_BYTES (NSTAGE * STAGE_WORDS * 4)   // 81920

__device__ __forceinline__ void mma_gemm(
    const __half* __restrict__ A, int lda,
    const __half* __restrict__ B, int ldb,
    int n_chunks, float* sm, float c[2][8][4])
{
    const int tid  = threadIdx.x;
    const int lane = tid & 31;
    const int wid  = tid >> 5;
    const int wm   = wid >> 1;
    const int wn   = wid & 1;
    const uint32_t sbase = smem_u32(sm);

    const int srow0 = tid >> 2;       // 0..63 (advance by 64)
    const int scc   = tid & 3;        // 16B chunk within row

    #pragma unroll
    for (int mt = 0; mt < 2; mt++)
        #pragma unroll
        for (int nt = 0; nt < 8; nt++)
            #pragma unroll
            for (int q = 0; q < 4; q++) c[mt][nt][q] = 0.f;

    auto issue = [&](int chunk, int stage) {
        if (chunk < n_chunks) {
            uint32_t sA = sbase + stage * (STAGE_WORDS * 4);
            uint32_t sB = sA + 128 * SROWH * 4;
            #pragma unroll
            for (int it = 0; it < 2; it++) {
                int row = srow0 + it * 64;
                const __half* ap = A + (size_t)row * lda + chunk * 32 + scc * 8;
                CP_ASYNC16(sA + (row * SROWH + scc * 4) * 4, ap);
                const __half* bp = B + (size_t)row * ldb + chunk * 32 + scc * 8;
                CP_ASYNC16(sB + (row * SROWH + scc * 4) * 4, bp);
            }
        }
        CP_COMMIT();
    };

    // ldmatrix lane-address offsets (bytes)
    const uint32_t aoff = ((uint32_t)(wm * 32 + (lane & 15)) * SROWH + (lane >> 4) * 4) * 4;
    const uint32_t boff = ((uint32_t)(wn * 64 + ((lane >> 4) & 1) * 8 + (lane & 7)) * SROWH
                           + ((lane >> 3) & 1) * 4) * 4;

    auto compute = [&](int s) {
        uint32_t sA = sbase + s * (STAGE_WORDS * 4);
        uint32_t sB = sA + 128 * SROWH * 4;
        uint32_t aAddr = sA + aoff;
        uint32_t bAddr = sB + boff;
        #pragma unroll
        for (int ks = 0; ks < 2; ks++) {
            uint32_t af[2][4];
            ldsm_x4(af[0], aAddr + ks * 32);
            ldsm_x4(af[1], aAddr + 16 * SROWH * 4 + ks * 32);
            #pragma unroll
            for (int j = 0; j < 4; j++) {
                uint32_t bb[4];
                ldsm_x4(bb, bAddr + j * 16 * SROWH * 4 + ks * 32);
                mma_f16(c[0][2*j],   af[0][0], af[0][1], af[0][2], af[0][3], bb[0], bb[1]);
                mma_f16(c[1][2*j],   af[1][0], af[1][1], af[1][2], af[1][3], bb[0], bb[1]);
                mma_f16(c[0][2*j+1], af[0][0], af[0][1], af[0][2], af[0][3], bb[2], bb[3]);
                mma_f16(c[1][2*j+1], af[1][0], af[1][1], af[1][2], af[1][3], bb[2], bb[3]);
            }
        }
    };

    issue(0, 0);
    issue(1, 1);
    issue(2, 2);
    for (int i = 0; i < n_chunks; i++) {
        CP_WAIT2();
        __syncthreads();           // single barrier per chunk
        compute(i & 3);
        issue(i + 3, (i + 3) & 3); // writes stage (i-1)&3, consumed before this barrier
    }
}

#define EPI_ROW(mt, half_)  (( (threadIdx.x >> 6) & 3 ) * 32 + (mt) * 16 + ((threadIdx.x & 31) >> 2) + (half_) * 8)
#define EPI_COL(nt)         (( (threadIdx.x >> 5) & 1 ) * 64 + (nt) * 8 + ((threadIdx.x & 31) & 3) * 2)

// ---------------------------------------------------------------- projection kernels

__global__ void __launch_bounds__(256, 2) qkv_gemm_kernel()
{
    extern __shared__ float sm[];
    int row0 = blockIdx.x * 128;
    int n0 = blockIdx.y * 128;

    float c[2][8][4];
    mma_gemm(g_xc + (size_t)row0 * D_IN, D_IN, g_wT + (size_t)n0 * D_IN, D_IN,
             D_IN / 32, sm, c);

    #pragma unroll
    for (int mt = 0; mt < 2; mt++)
        #pragma unroll
        for (int hf = 0; hf < 2; hf++) {
            int r = row0 + EPI_ROW(mt, hf);
            #pragma unroll
            for (int nt = 0; nt < 8; nt++) {
                int cl = EPI_COL(nt);
                float2 v;
                v.x = c[mt][nt][hf*2+0] + g_bias[n0 + cl];
                v.y = c[mt][nt][hf*2+1] + g_bias[n0 + cl + 1];
                *(float2*)&g_qkv[(size_t)r * QKV_N + n0 + cl] = v;
            }
        }
}

__global__ void __launch_bounds__(256, 2) outproj_gemm_kernel(
    const float* __restrict__ bo, float* __restrict__ out_o)
{
    extern __shared__ float sm[];
    int row0 = blockIdx.x * 128;
    int n0 = blockIdx.y * 128;

    float c[2][8][4];
    mma_gemm(g_attn + (size_t)row0 * D_IN, D_IN, g_woT + (size_t)n0 * D_IN, D_IN,
             D_IN / 32, sm, c);

    #pragma unroll
    for (int mt = 0; mt < 2; mt++)
        #pragma unroll
        for (int hf = 0; hf < 2; hf++) {
            int r = row0 + EPI_ROW(mt, hf);
            #pragma unroll
            for (int nt = 0; nt < 8; nt++) {
                int cl = EPI_COL(nt);
                float2 v;
                v.x = c[mt][nt][hf*2+0] + bo[n0 + cl];
                v.y = c[mt][nt][hf*2+1] + bo[n0 + cl + 1];
                *(float2*)&out_o[(size_t)r * D_IN + n0 + cl] = v;
            }
        }
}

// ---------------------------------------------------------------- fused flash attention (fp16, ldmatrix)
#define SROWFW 68
#define FLASH_TILE_W (128 * SROWFW)                   // 8704 words
#define FLASH_SMEM_BYTES ((3 * FLASH_TILE_W + 512) * 4)  // 106496

__global__ void __launch_bounds__(256, 1) flash_attn_kernel()
{
    extern __shared__ float sm[];
    uint32_t* KPw = (uint32_t*)sm + FLASH_TILE_W;
    float* redmax = sm + 3 * FLASH_TILE_W;   // [2][128]
    float* redsum = redmax + 256;            // [2][128]

    const int tid = threadIdx.x;
    const int lane = tid & 31;
    const int wid = tid >> 5;
    const int wm = wid >> 1;       // 0..3
    const int wn = wid & 1;        // 0..1

    const int bh = blockIdx.y;
    const int b = bh >> 4, h = bh & 15, g = h >> 3;
    const int bg = b * 2 + g;
    const int s0 = blockIdx.x * 128;

    const uint32_t sbase = smem_u32(sm);
    const uint32_t qb = sbase;
    const uint32_t kpb = sbase + FLASH_TILE_W * 4;
    const uint32_t vb = sbase + 2 * FLASH_TILE_W * 4;

    const int srow = tid >> 1;
    const int scb  = (tid & 1) * 8;

    // stage Q (group 0)
    {
        const __half* qsrc = g_q + (((size_t)b * HEADS + h) * SEQ + s0) * HD;
        #pragma unroll
        for (int q = 0; q < 8; q++)
            CP_ASYNC16(qb + (srow * SROWFW + (scb + q) * 4) * 4,
                       qsrc + (size_t)srow * HD + (scb + q) * 8);
        CP_COMMIT();
    }

    const __half* kptr = g_kc + ((size_t)b * T_TOT * GROUPS + g) * HD;
    const __half* vptr = g_vT + (size_t)bg * HD * T_TOT;

    float m_[2][2], l_[2][2], co[2][8][4];
    #pragma unroll
    for (int mt = 0; mt < 2; mt++)
        #pragma unroll
        for (int hf = 0; hf < 2; hf++) { m_[mt][hf] = -1e30f; l_[mt][hf] = 0.f; }
    #pragma unroll
    for (int mt = 0; mt < 2; mt++)
        #pragma unroll
        for (int nt = 0; nt < 8; nt++)
            #pragma unroll
            for (int q = 0; q < 4; q++) co[mt][nt][q] = 0.f;

    const uint32_t aoffF = ((uint32_t)(wm * 32 + (lane & 15)) * SROWFW + (lane >> 4) * 4) * 4;
    const uint32_t boffF = ((uint32_t)(wn * 64 + ((lane >> 4) & 1) * 8 + (lane & 7)) * SROWFW
                            + ((lane >> 3) & 1) * 4) * 4;
    const uint32_t aAddrQ = qb + aoffF;
    const uint32_t bAddrK = kpb + boffF;
    const uint32_t bAddrV = vb + boffF;
    const uint32_t aAddrP = kpb + aoffF;

    int myrow[2][2];
    #pragma unroll
    for (int mt = 0; mt < 2; mt++)
        #pragma unroll
        for (int hf = 0; hf < 2; hf++)
            myrow[mt][hf] = wm * 32 + mt * 16 + (lane >> 2) + hf * 8;

    for (int tc = 0; tc < T_TOT / 128; tc++) {
        const int t0 = tc * 128;
        #pragma unroll
        for (int q = 0; q < 8; q++)
            CP_ASYNC16(kpb + (srow * SROWFW + (scb + q) * 4) * 4,
                       kptr + (size_t)(t0 + srow) * (GROUPS * HD) + (scb + q) * 8);
        CP_COMMIT();
        #pragma unroll
        for (int q = 0; q < 8; q++)
            CP_ASYNC16(vb + (srow * SROWFW + (scb + q) * 4) * 4,
                       vptr + (size_t)srow * T_TOT + t0 + (scb + q) * 8);
        CP_COMMIT();
        CP_WAIT1();          // Q + K ready; V may lag
        __syncthreads();

        // ---- S = Q @ K^T
        float cs[2][8][4];
        #pragma unroll
        for (int mt = 0; mt < 2; mt++)
            #pragma unroll
            for (int nt = 0; nt < 8; nt++)
                #pragma unroll
                for (int q = 0; q < 4; q++) cs[mt][nt][q] = 0.f;

        #pragma unroll
        for (int ks = 0; ks < 8; ks++) {
            uint32_t af[2][4];
            ldsm_x4(af[0], aAddrQ + ks * 32);
            ldsm_x4(af[1], aAddrQ + 16 * SROWFW * 4 + ks * 32);
            #pragma unroll
            for (int j = 0; j < 4; j++) {
                uint32_t bb[4];
                ldsm_x4(bb, bAddrK + j * 16 * SROWFW * 4 + ks * 32);
                mma_f16(cs[0][2*j],   af[0][0], af[0][1], af[0][2], af[0][3], bb[0], bb[1]);
                mma_f16(cs[1][2*j],   af[1][0], af[1][1], af[1][2], af[1][3], bb[0], bb[1]);
                mma_f16(cs[0][2*j+1], af[0][0], af[0][1], af[0][2], af[0][3], bb[2], bb[3]);
                mma_f16(cs[1][2*j+1], af[1][0], af[1][1], af[1][2], af[1][3], bb[2], bb[3]);
            }
        }

        // ---- online softmax
        #pragma unroll
        for (int mt = 0; mt < 2; mt++)
            #pragma unroll
            for (int hf = 0; hf < 2; hf++) {
                float mx = -1e30f;
                #pragma unroll
                for (int nt = 0; nt < 8; nt++)
                    mx = fmaxf(mx, fmaxf(cs[mt][nt][hf*2], cs[mt][nt][hf*2+1]));
                mx = fmaxf(mx, __shfl_xor_sync(0xffffffffu, mx, 1));
                mx = fmaxf(mx, __shfl_xor_sync(0xffffffffu, mx, 2));
                if ((lane & 3) == 0) redmax[wn * 128 + myrow[mt][hf]] = mx;
            }
        __syncthreads();

        float sc[2][2];
        #pragma unroll
        for (int mt = 0; mt < 2; mt++)
            #pragma unroll
            for (int hf = 0; hf < 2; hf++) {
                int r = myrow[mt][hf];
                float mnew = fmaxf(m_[mt][hf], fmaxf(redmax[r], redmax[128 + r]));
                sc[mt][hf] = __expf(m_[mt][hf] - mnew);
                m_[mt][hf] = mnew;
            }

        // exp, partial sums, write P (fp16) into KP
        #pragma unroll
        for (int mt = 0; mt < 2; mt++)
            #pragma unroll
            for (int hf = 0; hf < 2; hf++) {
                int r = myrow[mt][hf];
                float mnew = m_[mt][hf];
                float sum = 0.f;
                __half2* prow = (__half2*)KPw + r * SROWFW + wn * 32 + (lane & 3);
                #pragma unroll
                for (int nt = 0; nt < 8; nt++) {
                    float p0 = __expf(cs[mt][nt][hf*2+0] - mnew);
                    float p1 = __expf(cs[mt][nt][hf*2+1] - mnew);
                    sum += p0 + p1;
                    prow[nt * 4] = __floats2half2_rn(p0, p1);
                }
                sum += __shfl_xor_sync(0xffffffffu, sum, 1);
                sum += __shfl_xor_sync(0xffffffffu, sum, 2);
                if ((lane & 3) == 0) redsum[wn * 128 + r] = sum;
            }
        CP_WAIT0();
        __syncthreads();   // P + redsum + V visible

        #pragma unroll
        for (int mt = 0; mt < 2; mt++)
            #pragma unroll
            for (int hf = 0; hf < 2; hf++) {
                int r = myrow[mt][hf];
                l_[mt][hf] = l_[mt][hf] * sc[mt][hf] + redsum[r] + redsum[128 + r];
                #pragma unroll
                for (int nt = 0; nt < 8; nt++) {
                    co[mt][nt][hf*2+0] *= sc[mt][hf];
                    co[mt][nt][hf*2+1] *= sc[mt][hf];
                }
            }

        // ---- O += P @ V^T
        #pragma unroll
        for (int ks = 0; ks < 8; ks++) {
            uint32_t af[2][4];
            ldsm_x4(af[0], aAddrP + ks * 32);
            ldsm_x4(af[1], aAddrP + 16 * SROWFW * 4 + ks * 32);
            #pragma unroll
            for (int j = 0; j < 4; j++) {
                uint32_t bb[4];
                ldsm_x4(bb, bAddrV + j * 16 * SROWFW * 4 + ks * 32);
                mma_f16(co[0][2*j],   af[0][0], af[0][1], af[0][2], af[0][3], bb[0], bb[1]);
                mma_f16(co[1][2*j],   af[1][0], af[1][1], af[1][2], af[1][3], bb[0], bb[1]);
                mma_f16(co[0][2*j+1], af[0][0], af[0][1], af[0][2], af[0][3], bb[2], bb[3]);
                mma_f16(co[1][2*j+1], af[1][0], af[1][1], af[1][2], af[1][3], bb[2], bb[3]);
            }
        }
        __syncthreads();
    }

    // ---- epilogue: normalize, write g_attn (fp16)
    #pragma unroll
    for (int mt = 0; mt < 2; mt++)
        #pragma unroll
        for (int hf = 0; hf < 2; hf++) {
            int r = myrow[mt][hf];
            float inv = 1.f / l_[mt][hf];
            __half2* dst = (__half2*)(g_attn + ((size_t)b * SEQ + s0 + r) * D_IN
                                      + h * HD + wn * 64 + (lane & 3) * 2);
            #pragma unroll
            for (int nt = 0; nt < 8; nt++)
                dst[nt * 4] = __floats2half2_rn(co[mt][nt][hf*2+0] * inv,
                                                co[mt][nt][hf*2+1] * inv);
        }
}

// ---------------------------------------------------------------- prep kernels

__global__ void cvt_x_kernel(const float* __restrict__ x)
{
    int i = blockIdx.x * blockDim.x + threadIdx.x;
    float4 v = ((const float4*)x)[i];
    ((__half2*)g_xc)[i * 2 + 0] = __floats2half2_rn(v.x, v.y);
    ((__half2*)g_xc)[i * 2 + 1] = __floats2half2_rn(v.z, v.w);
}

__device__ __forceinline__ void transpose_block(
    const float* __restrict__ src, __half* __restrict__ dst,
    int K, int N, int bx, int by, float* tbuf)
{
    int n0 = bx * 32, k0 = by * 32;
    int tx = threadIdx.x, ty = threadIdx.y;
    #pragma unroll
    for (int j = 0; j < 32; j += 8)
        tbuf[(ty + j) * 33 + tx] = src[(size_t)(k0 + ty + j) * N + n0 + tx];
    __syncthreads();
    #pragma unroll
    for (int j = 0; j < 32; j += 8)
        dst[(size_t)(n0 + ty + j) * K + k0 + tx] = __float2half(tbuf[tx * 33 + ty + j]);
}

// All weight transposes + bias combine, one launch. blockDim (32,8).
__global__ void prep_weights_kernel(
    const float* __restrict__ Wq, const float* __restrict__ Wk,
    const float* __restrict__ Wv, const float* __restrict__ Wo,
    const float* __restrict__ bq, const float* __restrict__ bk,
    const float* __restrict__ bv)
{
    __shared__ float tbuf[32 * 33];
    int bid = blockIdx.x;
    if (bid < 4096) {
        transpose_block(Wq, g_wT, D_IN, D_IN, bid & 63, bid >> 6, tbuf);
    } else if (bid < 4608) {
        int l = bid - 4096;
        transpose_block(Wk, g_wT + 2048 * D_IN, D_IN, 256, l & 7, l >> 3, tbuf);
    } else if (bid < 5120) {
        int l = bid - 4608;
        transpose_block(Wv, g_wT + 2304 * D_IN, D_IN, 256, l & 7, l >> 3, tbuf);
    } else if (bid < 9216) {
        int l = bid - 5120;
        transpose_block(Wo, g_woT, D_IN, D_IN, l & 63, l >> 6, tbuf);
    } else {
        int i = (bid - 9216) * 256 + threadIdx.y * 32 + threadIdx.x;
        if (i < QKV_N) {
            float v;
            if (i < 2048) v = bq[i];
            else if (i < 2304) v = bk[i - 2048];
            else v = bv[i - 2304];
            g_bias[i] = v;
        }
    }
}

// rope_q + rope_kv fused
#define NQ_THREADS (M_ROWS * HEADS * 64)    // 4194304
#define NKV_THREADS (M_ROWS * GROUPS * 64)  // 524288
__global__ void rope_all_kernel(float* __restrict__ out_k, float* __restrict__ out_v)
{
    int idx = blockIdx.x * blockDim.x + threadIdx.x;
    if (idx < NQ_THREADS) {
        int j = idx & 63;
        int h = (idx >> 6) & 15;
        int m = idx >> 10;
        const float* src = g_qkv + (size_t)m * QKV_N + h * HD;
        float x1 = src[j], x2 = src[j + 64];
        int s = m & 511, b = m >> 9;
        float pos = (float)(CACHE + s);
        float freq = pos * expf(-(float)j * (9.210340371976184f / 64.f));
        float sn, cs; sincosf(freq, &sn, &cs);
        const float SCALE = 0.08838834764831845f;
        __half* dst = g_q + (((size_t)b * HEADS + h) * SEQ + s) * HD;
        dst[j]      = __float2half((x1 * cs - x2 * sn) * SCALE);
        dst[j + 64] = __float2half((x2 * cs + x1 * sn) * SCALE);
    } else {
        int kidx = idx - NQ_THREADS;
        int j = kidx & 63;
        int g = (kidx >> 6) & 1;
        int m = kidx >> 7;
        const float* ksrc = g_qkv + (size_t)m * QKV_N + 2048 + g * HD;
        const float* vsrc = g_qkv + (size_t)m * QKV_N + 2304 + g * HD;
        float x1 = ksrc[j], x2 = ksrc[j + 64];
        int s = m & 511, b = m >> 9;
        float pos = (float)(CACHE + s);
        float freq = pos * expf(-(float)j * (9.210340371976184f / 64.f));
        float sn, cs; sincosf(freq, &sn, &cs);
        float k1 = x1 * cs - x2 * sn;
        float k2 = x2 * cs + x1 * sn;
        size_t base = (((size_t)b * T_TOT + CACHE + s) * GROUPS + g) * HD;
        out_k[base + j]      = k1;
        out_k[base + j + 64] = k2;
        g_kc[base + j]       = __float2half(k1);
        g_kc[base + j + 64]  = __float2half(k2);
        float v1 = vsrc[j], v2 = vsrc[j + 64];
        out_v[base + j]      = v1;
        out_v[base + j + 64] = v2;
        int bg = b * 2 + g;
        g_vT[(size_t)bg * HD * T_TOT + (size_t)j * T_TOT + CACHE + s]        = __float2half(v1);
        g_vT[(size_t)bg * HD * T_TOT + (size_t)(j + 64) * T_TOT + CACHE + s] = __float2half(v2);
    }
}

// prev cache copy + fp16 K cache + transposed-V history
__global__ void copy_prev_kernel(const float* __restrict__ prev_k,
                                 const float* __restrict__ prev_v,
                                 float* __restrict__ out_k,
                                 float* __restrict__ out_v)
{
    int idx = blockIdx.x * blockDim.x + threadIdx.x;
    if (idx >= BATCH * CACHE * GROUPS * HD) return;
    int b = idx >> 16;
    int r = idx & 65535;                 // ((t*GROUPS+g)*HD + hd)
    float kv = prev_k[idx];
    float vv = prev_v[idx];
    out_k[(size_t)b * (T_TOT * GROUPS * HD) + r] = kv;
    g_kc[(size_t)b * (T_TOT * GROUPS * HD) + r]  = __float2half(kv);
    out_v[(size_t)b * (T_TOT * GROUPS * HD) + r] = vv;
    int t = r >> 8;
    int g = (r >> 7) & 1;
    int hd = r & 127;
    g_vT[(size_t)(b * 2 + g) * HD * T_TOT + (size_t)hd * T_TOT + t] = __float2half(vv);
}

// ---------------------------------------------------------------- launcher
extern "C" void kernel_launch(void* const* d_in, const int* in_sizes, int n_in,
                              void* d_out, int out_size)
{
    const float* x      = (const float*)d_in[0];
    const float* prev_k = (const float*)d_in[1];
    const float* prev_v = (const float*)d_in[2];
    const float* Wq     = (const float*)d_in[3];
    const float* bq     = (const float*)d_in[4];
    const float* Wk     = (const float*)d_in[5];
    const float* bk     = (const float*)d_in[6];
    const float* Wv     = (const float*)d_in[7];
    const float* bv     = (const float*)d_in[8];
    const float* Wo     = (const float*)d_in[9];
    const float* bo     = (const float*)d_in[10];

    float* out_o = (float*)d_out;
    float* out_k = out_o + OUT_O_SIZE;
    float* out_v = out_k + OUT_K_SIZE;

    static bool attr_set = false;
    if (!attr_set) {
        cudaFuncSetAttribute(qkv_gemm_kernel,     cudaFuncAttributeMaxDynamicSharedMemorySize, GEMM_SMEM_BYTES);
        cudaFuncSetAttribute(outproj_gemm_kernel, cudaFuncAttributeMaxDynamicSharedMemorySize, GEMM_SMEM_BYTES);
        cudaFuncSetAttribute(flash_attn_kernel,   cudaFuncAttributeMaxDynamicSharedMemorySize, FLASH_SMEM_BYTES);
        attr_set = true;
    }

    // 0. Operand preparation (2 launches)
    cvt_x_kernel<<<(M_ROWS * D_IN / 4) / 256, 256>>>(x);
    prep_weights_kernel<<<9226, dim3(32, 8)>>>(Wq, Wk, Wv, Wo, bq, bk, bv);

    // 1. kv-cache history
    copy_prev_kernel<<<2048, 256>>>(prev_k, prev_v, out_k, out_v);

    // 2. QKV projection
    qkv_gemm_kernel<<<dim3(M_ROWS / 128, QKV_N / 128), 256, GEMM_SMEM_BYTES>>>();

    // 3. RoPE q + k + v copy + transposed V (one launch)
    rope_all_kernel<<<(NQ_THREADS + NKV_THREADS) / 256, 256>>>(out_k, out_v);

    // 4. Fused flash attention
    flash_attn_kernel<<<dim3(SEQ / 128, BATCH * HEADS), 256, FLASH_SMEM_BYTES>>>();

    // 5. Output projection
    outproj_gemm_kernel<<<dim3(M_ROWS / 128, D_IN / 128), 256, GEMM_SMEM_BYTES>>>(bo, out_o);
}